// round 14
// baseline (speedup 1.0000x reference)
#include <cuda_runtime.h>
#include <cuda_fp16.h>
#include <cstdint>

#define N_NODES 50000
#define N_EDGES 800000
#define HID 128
#define OUTD 64
#define BN_EPS 1e-5f

// ---------------- scratch (device globals: allocation-free) ----------------
__device__ int   g_cnt[N_NODES];
__device__ int   g_rank[N_EDGES];
__device__ int   g_rowptr[N_NODES + 1];
__device__ __align__(16) int2 g_edge[N_EDGES];      // {src, dinv[src] bits} CSR-ordered
__device__ float g_dinv[N_NODES];
__device__ __align__(16) __half g_hp16[(size_t)N_NODES * HID];   // X@W (UNSCALED), fp16
__device__ __align__(16) __half g_act16[(size_t)N_NODES * HID];  // post agg+BN+ReLU, fp16
__device__ __align__(16) __half g_wf16[5 * 16384];  // fp16 weights, n-major [n][128]

// ---------------- CSR build ----------------
__global__ void hist_kernel(const int* __restrict__ dst) {
    int e = blockIdx.x * blockDim.x + threadIdx.x;
    if (e < N_EDGES) g_rank[e] = atomicAdd(&g_cnt[dst[e]], 1);
}
__global__ void scan_dinv_kernel() {
    __shared__ int warp_sums[32];
    __shared__ int carry_sh;
    const int lane = threadIdx.x & 31, wid = threadIdx.x >> 5;
    if (threadIdx.x == 0) carry_sh = 0;
    __syncthreads();
    for (int base = 0; base < N_NODES; base += 8192) {
        const int c = carry_sh;
        const int idx0 = base + (int)threadIdx.x * 8;
        int v[8];
        if (idx0 + 8 <= N_NODES) {
            int4 a = *reinterpret_cast<const int4*>(g_cnt + idx0);
            int4 b = *reinterpret_cast<const int4*>(g_cnt + idx0 + 4);
            v[0] = a.x; v[1] = a.y; v[2] = a.z; v[3] = a.w;
            v[4] = b.x; v[5] = b.y; v[6] = b.z; v[7] = b.w;
        } else {
#pragma unroll
            for (int j = 0; j < 8; j++) v[j] = (idx0 + j < N_NODES) ? g_cnt[idx0 + j] : 0;
        }
        int p[8];
        p[0] = v[0];
#pragma unroll
        for (int j = 1; j < 8; j++) p[j] = p[j - 1] + v[j];
#pragma unroll
        for (int j = 0; j < 8; j++)
            if (idx0 + j < N_NODES) g_dinv[idx0 + j] = rsqrtf(1.0f + (float)v[j]);
        const int tot = p[7];
        int x = tot;
#pragma unroll
        for (int o = 1; o < 32; o <<= 1) {
            int y = __shfl_up_sync(0xffffffffu, x, o);
            if (lane >= o) x += y;
        }
        if (lane == 31) warp_sums[wid] = x;
        __syncthreads();
        if (wid == 0) {
            int s = warp_sums[lane];
#pragma unroll
            for (int o = 1; o < 32; o <<= 1) {
                int y = __shfl_up_sync(0xffffffffu, s, o);
                if (lane >= o) s += y;
            }
            warp_sums[lane] = s;
        }
        __syncthreads();
        const int basep = c + (wid > 0 ? warp_sums[wid - 1] : 0) + (x - tot);
#pragma unroll
        for (int j = 0; j < 8; j++)
            if (idx0 + j < N_NODES) g_rowptr[idx0 + j + 1] = basep + p[j];
        __syncthreads();
        if (threadIdx.x == 0) carry_sh = c + warp_sums[31];
        __syncthreads();
    }
    if (threadIdx.x == 0) g_rowptr[0] = 0;
}
__global__ void fill_csr_kernel(const int* __restrict__ src, const int* __restrict__ dst) {
    int e = blockIdx.x * blockDim.x + threadIdx.x;
    if (e < N_EDGES) {
        int s = src[e];
        int p = g_rowptr[dst[e]] + g_rank[e];
        g_edge[p] = make_int2(s, __float_as_int(g_dinv[s]));
    }
}

// ---------------- helpers ----------------
__device__ __forceinline__ void mma16816_f16(float* d, const uint32_t* a, const uint32_t* b) {
    asm volatile(
        "mma.sync.aligned.m16n8k16.row.col.f32.f16.f16.f32 "
        "{%0,%1,%2,%3}, {%4,%5,%6,%7}, {%8,%9}, {%0,%1,%2,%3};"
        : "+f"(d[0]), "+f"(d[1]), "+f"(d[2]), "+f"(d[3])
        : "r"(a[0]), "r"(a[1]), "r"(a[2]), "r"(a[3]), "r"(b[0]), "r"(b[1]));
}

// ---- weight prep: all 5 slots fp16, n-major [n][128] ----
__global__ void prep_w_kernel(const float* __restrict__ W0, const float* __restrict__ W1,
                              const float* __restrict__ W2, const float* __restrict__ Wm1,
                              const float* __restrict__ Wm2) {
    int idx = blockIdx.x * blockDim.x + threadIdx.x;
    int slot = idx >> 14, i = idx & 16383;
    if (slot >= 5) return;
    const float* W;
    int K, NC;
    if (slot == 0) { W = W0; K = 64; NC = 128; }
    else if (slot == 1) { W = W1; K = 128; NC = 128; }
    else if (slot == 2) { W = W2; K = 128; NC = 128; }
    else if (slot == 3) { W = Wm1; K = 128; NC = 128; }
    else { W = Wm2; K = 128; NC = 64; }
    if (i >= K * NC) return;
    int k = i / NC, n = i % NC;
    g_wf16[slot * 16384 + n * 128 + k] = __float2half_rn(W[i]);
}

// ---------------- fp16 HMMA GEMM: g_hp16 = X[128 x K] @ W  (unscaled) -------------
// SRCSEL: 0 = external fp32 X (K=64), 1 = g_act16 fp16 (K=128)
template <int K, int SRCSEL>
__global__ __launch_bounds__(256) void mma_gemm_f16_kernel(const float* __restrict__ Xext,
                                                           const __half* __restrict__ wf) {
    constexpr int LDA = 72;
    extern __shared__ __align__(16) char smem[];
    __half* As = (__half*)smem;                // [128][72]
    __half* Bs = As + 128 * LDA;               // [128][72]

    const int tid = threadIdx.x, wid = tid >> 5, lane = tid & 31;
    const int row0 = blockIdx.x * 128;
    const int m0 = (wid >> 1) * 32, n0 = (wid & 1) * 64;
    const int gid = lane >> 2, tid4 = lane & 3;

    float acc[2][8][4];
#pragma unroll
    for (int mi = 0; mi < 2; mi++)
#pragma unroll
        for (int ni = 0; ni < 8; ni++)
#pragma unroll
            for (int j = 0; j < 4; j++) acc[mi][ni][j] = 0.f;

    for (int kc = 0; kc < K; kc += 64) {
        if (kc) __syncthreads();
        // A chunk fill
#pragma unroll
        for (int it = 0; it < 8; it++) {
            int i = tid + it * 256;
            int r = i >> 4, q = (i & 15) * 4;
            uint2 u = make_uint2(0u, 0u);
            if (row0 + r < N_NODES) {
                if (SRCSEL == 0) {
                    float4 v = *reinterpret_cast<const float4*>(
                        Xext + (size_t)(row0 + r) * K + kc + q);
                    __half2 p0 = __floats2half2_rn(v.x, v.y);
                    __half2 p1 = __floats2half2_rn(v.z, v.w);
                    u = make_uint2(*reinterpret_cast<uint32_t*>(&p0),
                                   *reinterpret_cast<uint32_t*>(&p1));
                } else {
                    u = *reinterpret_cast<const uint2*>(
                        g_act16 + (size_t)(row0 + r) * HID + kc + q);
                }
            }
            *reinterpret_cast<uint2*>(As + r * LDA + q) = u;
        }
        // B chunk fill: pure copy from pre-converted fp16 weights
#pragma unroll
        for (int it = 0; it < 8; it++) {
            int i = tid + it * 256;
            int n = i >> 4, q = (i & 15) * 4;
            *reinterpret_cast<uint2*>(Bs + n * LDA + q) =
                *reinterpret_cast<const uint2*>(wf + n * 128 + kc + q);
        }
        __syncthreads();

#pragma unroll
        for (int k16 = 0; k16 < 64; k16 += 16) {
            uint32_t bh[8][2];
#pragma unroll
            for (int ni = 0; ni < 8; ni++) {
                const __half* bp = Bs + (n0 + ni * 8 + gid) * LDA + k16 + tid4 * 2;
                bh[ni][0] = *reinterpret_cast<const uint32_t*>(bp);
                bh[ni][1] = *reinterpret_cast<const uint32_t*>(bp + 8);
            }
#pragma unroll
            for (int mi = 0; mi < 2; mi++) {
                const int r = m0 + mi * 16 + gid, c = k16 + tid4 * 2;
                uint32_t ah[4];
                ah[0] = *reinterpret_cast<const uint32_t*>(As + r * LDA + c);
                ah[1] = *reinterpret_cast<const uint32_t*>(As + (r + 8) * LDA + c);
                ah[2] = *reinterpret_cast<const uint32_t*>(As + r * LDA + c + 8);
                ah[3] = *reinterpret_cast<const uint32_t*>(As + (r + 8) * LDA + c + 8);
#pragma unroll
                for (int ni = 0; ni < 8; ni++) mma16816_f16(acc[mi][ni], ah, bh[ni]);
            }
        }
    }

#pragma unroll
    for (int mi = 0; mi < 2; mi++)
#pragma unroll
        for (int rr = 0; rr < 2; rr++) {
            int r = row0 + m0 + mi * 16 + gid + rr * 8;
            if (r < N_NODES) {
#pragma unroll
                for (int ni = 0; ni < 8; ni++) {
                    int cn = n0 + ni * 8 + tid4 * 2;
                    __half2 o = __floats2half2_rn(acc[mi][ni][rr * 2],
                                                  acc[mi][ni][rr * 2 + 1]);
                    *reinterpret_cast<__half2*>(g_hp16 + (size_t)r * HID + cn) = o;
                }
            }
        }
}

// ---- CSR aggregation: masked full-width 8-edge batches (no serial tail) ----------
__global__ __launch_bounds__(256) void agg_bn_kernel(const float* __restrict__ bias,
                                                     const float* __restrict__ gam,
                                                     const float* __restrict__ bet,
                                                     const float* __restrict__ mu,
                                                     const float* __restrict__ var) {
    int n = (blockIdx.x * 256 + threadIdx.x) >> 5;
    int lane = threadIdx.x & 31;
    if (n >= N_NODES) return;

    const __half* hp = g_hp16;
    const float dn = g_dinv[n];
    float4 acc;
    {
        uint2 u = *reinterpret_cast<const uint2*>(hp + (size_t)n * HID + lane * 4);
        float2 f0 = __half22float2(*reinterpret_cast<__half2*>(&u.x));
        float2 f1 = __half22float2(*reinterpret_cast<__half2*>(&u.y));
        acc = make_float4(dn * f0.x, dn * f0.y, dn * f1.x, dn * f1.y);
    }

    const int e0 = g_rowptr[n];
    const int e1 = g_rowptr[n + 1];
    // every batch is full-width: OOB lanes clamp to e1-1 and zero their coef,
    // so all 16 loads per batch are independent (MLP=8 on every iteration).
    for (int e = e0; e < e1; e += 8) {
        int2 ec[8];
#pragma unroll
        for (int j = 0; j < 8; j++) {
            int idx = (e + j < e1) ? (e + j) : (e1 - 1);
            ec[j] = g_edge[idx];
        }
#pragma unroll
        for (int j = 0; j < 8; j++)
            if (e + j >= e1) ec[j].y = 0;   // zero coefficient for padded lanes
        uint2 u[8];
#pragma unroll
        for (int j = 0; j < 8; j++)
            u[j] = *reinterpret_cast<const uint2*>(hp + (size_t)ec[j].x * HID + lane * 4);
#pragma unroll
        for (int j = 0; j < 8; j++) {
            float c = __int_as_float(ec[j].y);
            float2 f0 = __half22float2(*reinterpret_cast<__half2*>(&u[j].x));
            float2 f1 = __half22float2(*reinterpret_cast<__half2*>(&u[j].y));
            acc.x = fmaf(c, f0.x, acc.x);
            acc.y = fmaf(c, f0.y, acc.y);
            acc.z = fmaf(c, f1.x, acc.z);
            acc.w = fmaf(c, f1.y, acc.w);
        }
    }

    float4 gg = reinterpret_cast<const float4*>(gam)[lane];
    float4 vv = reinterpret_cast<const float4*>(var)[lane];
    float4 mm = reinterpret_cast<const float4*>(mu)[lane];
    float4 be = reinterpret_cast<const float4*>(bet)[lane];
    float4 bb = reinterpret_cast<const float4*>(bias)[lane];
    float4 o;
    {
        float s;
        s = gg.x * rsqrtf(vv.x + BN_EPS); o.x = fmaxf((dn * acc.x + bb.x - mm.x) * s + be.x, 0.f);
        s = gg.y * rsqrtf(vv.y + BN_EPS); o.y = fmaxf((dn * acc.y + bb.y - mm.y) * s + be.y, 0.f);
        s = gg.z * rsqrtf(vv.z + BN_EPS); o.z = fmaxf((dn * acc.z + bb.z - mm.z) * s + be.z, 0.f);
        s = gg.w * rsqrtf(vv.w + BN_EPS); o.w = fmaxf((dn * acc.w + bb.w - mm.w) * s + be.w, 0.f);
    }
    __half2 h0 = __floats2half2_rn(o.x, o.y);
    __half2 h1 = __floats2half2_rn(o.z, o.w);
    *reinterpret_cast<uint2*>(g_act16 + (size_t)n * HID + lane * 4) =
        make_uint2(*reinterpret_cast<uint32_t*>(&h0), *reinterpret_cast<uint32_t*>(&h1));
}

// ---------------- fused MLP head: both stages fp16 --------------------------------
__global__ __launch_bounds__(256) void mlp_head_kernel(const float* __restrict__ bm1,
                                                       const float* __restrict__ bm2,
                                                       const __half* __restrict__ w1f,
                                                       const __half* __restrict__ w2f,
                                                       float* __restrict__ outext) {
    constexpr int LDA = 136, LDB = 72;
    extern __shared__ __align__(16) char smem[];
    __half* As16 = (__half*)smem;                      // [128][136] A / later H
    __half* Bs16 = (__half*)(smem + 34816);            // [128][136] Wm1
    __half* B2 = (__half*)(smem + 69632);              // [64][72] Wm2 chunk

    const int tid = threadIdx.x, wid = tid >> 5, lane = tid & 31;
    const int row0 = blockIdx.x * 128;
    const int gid = lane >> 2, tid4 = lane & 3;

#pragma unroll
    for (int it = 0; it < 8; it++) {
        int i = tid + it * 256;
        int r = i >> 4, q = (i & 15) * 8;
        uint4 u = make_uint4(0u, 0u, 0u, 0u);
        if (row0 + r < N_NODES)
            u = *reinterpret_cast<const uint4*>(g_act16 + (size_t)(row0 + r) * HID + q);
        *reinterpret_cast<uint4*>(As16 + r * LDA + q) = u;
    }
#pragma unroll
    for (int it = 0; it < 8; it++) {
        int i = tid + it * 256;
        int n = i >> 4, q = (i & 15) * 8;
        *reinterpret_cast<uint4*>(Bs16 + n * LDA + q) =
            *reinterpret_cast<const uint4*>(w1f + n * 128 + q);
    }
    __syncthreads();

    const int m0 = (wid >> 1) * 32, n0 = (wid & 1) * 64;
    float acc[2][8][4];
#pragma unroll
    for (int mi = 0; mi < 2; mi++)
#pragma unroll
        for (int ni = 0; ni < 8; ni++)
#pragma unroll
            for (int j = 0; j < 4; j++) acc[mi][ni][j] = 0.f;

#pragma unroll
    for (int k16 = 0; k16 < 128; k16 += 16) {
        uint32_t bh[8][2];
#pragma unroll
        for (int ni = 0; ni < 8; ni++) {
            const __half* bp = Bs16 + (n0 + ni * 8 + gid) * LDA + k16 + tid4 * 2;
            bh[ni][0] = *reinterpret_cast<const uint32_t*>(bp);
            bh[ni][1] = *reinterpret_cast<const uint32_t*>(bp + 8);
        }
#pragma unroll
        for (int mi = 0; mi < 2; mi++) {
            const int r = m0 + mi * 16 + gid, c = k16 + tid4 * 2;
            uint32_t ah[4];
            ah[0] = *reinterpret_cast<const uint32_t*>(As16 + r * LDA + c);
            ah[1] = *reinterpret_cast<const uint32_t*>(As16 + (r + 8) * LDA + c);
            ah[2] = *reinterpret_cast<const uint32_t*>(As16 + r * LDA + c + 8);
            ah[3] = *reinterpret_cast<const uint32_t*>(As16 + (r + 8) * LDA + c + 8);
#pragma unroll
            for (int ni = 0; ni < 8; ni++) mma16816_f16(acc[mi][ni], ah, bh[ni]);
        }
    }
    __syncthreads();

#pragma unroll
    for (int mi = 0; mi < 2; mi++)
#pragma unroll
        for (int rr = 0; rr < 2; rr++) {
            int lr = m0 + mi * 16 + gid + rr * 8;
#pragma unroll
            for (int ni = 0; ni < 8; ni++) {
                int cn = n0 + ni * 8 + tid4 * 2;
                float2 bb = *reinterpret_cast<const float2*>(bm1 + cn);
                __half2 h = __floats2half2_rn(fmaxf(acc[mi][ni][rr * 2] + bb.x, 0.f),
                                              fmaxf(acc[mi][ni][rr * 2 + 1] + bb.y, 0.f));
                *reinterpret_cast<__half2*>(As16 + lr * LDA + cn) = h;
            }
        }
    __syncthreads();

    const int n02 = (wid & 1) * 32;
    float acc2[2][4][4];
#pragma unroll
    for (int mi = 0; mi < 2; mi++)
#pragma unroll
        for (int ni = 0; ni < 4; ni++)
#pragma unroll
            for (int j = 0; j < 4; j++) acc2[mi][ni][j] = 0.f;

    for (int kc = 0; kc < 128; kc += 64) {
        if (kc) __syncthreads();
#pragma unroll
        for (int it = 0; it < 4; it++) {
            int i = tid + it * 256;
            int n = i >> 4, q = (i & 15) * 4;
            *reinterpret_cast<uint2*>(B2 + n * LDB + q) =
                *reinterpret_cast<const uint2*>(w2f + n * 128 + kc + q);
        }
        __syncthreads();
#pragma unroll
        for (int k16 = 0; k16 < 64; k16 += 16) {
            uint32_t bh[4][2];
#pragma unroll
            for (int ni = 0; ni < 4; ni++) {
                const __half* bp = B2 + (n02 + ni * 8 + gid) * LDB + k16 + tid4 * 2;
                bh[ni][0] = *reinterpret_cast<const uint32_t*>(bp);
                bh[ni][1] = *reinterpret_cast<const uint32_t*>(bp + 8);
            }
#pragma unroll
            for (int mi = 0; mi < 2; mi++) {
                const int r = m0 + mi * 16 + gid, c = kc + k16 + tid4 * 2;
                uint32_t ah[4];
                ah[0] = *reinterpret_cast<const uint32_t*>(As16 + r * LDA + c);
                ah[1] = *reinterpret_cast<const uint32_t*>(As16 + (r + 8) * LDA + c);
                ah[2] = *reinterpret_cast<const uint32_t*>(As16 + r * LDA + c + 8);
                ah[3] = *reinterpret_cast<const uint32_t*>(As16 + (r + 8) * LDA + c + 8);
#pragma unroll
                for (int ni = 0; ni < 4; ni++) mma16816_f16(acc2[mi][ni], ah, bh[ni]);
            }
        }
    }

#pragma unroll
    for (int mi = 0; mi < 2; mi++)
#pragma unroll
        for (int rr = 0; rr < 2; rr++) {
            int r = row0 + m0 + mi * 16 + gid + rr * 8;
            if (r < N_NODES) {
#pragma unroll
                for (int ni = 0; ni < 4; ni++) {
                    int cn = n02 + ni * 8 + tid4 * 2;
                    float2 bb = *reinterpret_cast<const float2*>(bm2 + cn);
                    float2 o = make_float2(acc2[mi][ni][rr * 2] + bb.x,
                                           acc2[mi][ni][rr * 2 + 1] + bb.y);
                    *reinterpret_cast<float2*>(outext + (size_t)r * OUTD + cn) = o;
                }
            }
        }
}

// ---------------- launch ----------------
extern "C" void kernel_launch(void* const* d_in, const int* in_sizes, int n_in,
                              void* d_out, int out_size) {
    (void)in_sizes; (void)n_in; (void)out_size;
    const float* x   = (const float*)d_in[0];
    const int*   src = (const int*)d_in[1];
    const int*   dst = (const int*)d_in[2];
    const float* W0 = (const float*)d_in[3],  *b0 = (const float*)d_in[4];
    const float* g0 = (const float*)d_in[5],  *be0 = (const float*)d_in[6];
    const float* m0 = (const float*)d_in[7],  *v0 = (const float*)d_in[8];
    const float* W1 = (const float*)d_in[9],  *b1 = (const float*)d_in[10];
    const float* g1 = (const float*)d_in[11], *be1 = (const float*)d_in[12];
    const float* m1 = (const float*)d_in[13], *v1 = (const float*)d_in[14];
    const float* W2 = (const float*)d_in[15], *b2 = (const float*)d_in[16];
    const float* g2 = (const float*)d_in[17], *be2 = (const float*)d_in[18];
    const float* m2 = (const float*)d_in[19], *v2 = (const float*)d_in[20];
    const float* Wm1 = (const float*)d_in[21], *bm1 = (const float*)d_in[22];
    const float* Wm2 = (const float*)d_in[23], *bm2 = (const float*)d_in[24];
    float* out = (float*)d_out;

    const int NB_EDGE = (N_EDGES + 255) / 256;
    const int NB_GEMM = (N_NODES + 127) / 128;
    const int NB_AGG  = (N_NODES + 7) / 8;

    constexpr int SM_F = (128 * 72 + 128 * 72) * 2;     // 36864
    constexpr int SM_H = 69632 + 64 * 72 * 2;           // 78848

    cudaFuncSetAttribute(mma_gemm_f16_kernel<64, 0>,
                         cudaFuncAttributeMaxDynamicSharedMemorySize, SM_F);
    cudaFuncSetAttribute(mma_gemm_f16_kernel<128, 1>,
                         cudaFuncAttributeMaxDynamicSharedMemorySize, SM_F);
    cudaFuncSetAttribute(mlp_head_kernel,
                         cudaFuncAttributeMaxDynamicSharedMemorySize, SM_H);

    __half* wf_dev = nullptr;
    int* cnt_dev = nullptr;
    cudaGetSymbolAddress((void**)&wf_dev, g_wf16);
    cudaGetSymbolAddress((void**)&cnt_dev, g_cnt);

    // side stream for CSR build
    static cudaStream_t s2 = nullptr;
    static cudaEvent_t evFork = nullptr, evJoin = nullptr;
    if (s2 == nullptr) {
        cudaStreamCreateWithFlags(&s2, cudaStreamNonBlocking);
        cudaEventCreateWithFlags(&evFork, cudaEventDisableTiming);
        cudaEventCreateWithFlags(&evJoin, cudaEventDisableTiming);
    }

    cudaEventRecord(evFork, 0);
    cudaStreamWaitEvent(s2, evFork, 0);
    cudaMemsetAsync(cnt_dev, 0, N_NODES * sizeof(int), s2);
    hist_kernel<<<NB_EDGE, 256, 0, s2>>>(dst);
    scan_dinv_kernel<<<1, 1024, 0, s2>>>();
    fill_csr_kernel<<<NB_EDGE, 256, 0, s2>>>(src, dst);
    cudaEventRecord(evJoin, s2);

    // main stream: weights + layer-0 GEMM (dinv-independent)
    prep_w_kernel<<<(5 * 16384 + 255) / 256, 256>>>(W0, W1, W2, Wm1, Wm2);
    mma_gemm_f16_kernel<64, 0><<<NB_GEMM, 256, SM_F>>>(x, wf_dev);

    cudaStreamWaitEvent(0, evJoin, 0);

    agg_bn_kernel<<<NB_AGG, 256>>>(b0, g0, be0, m0, v0);
    mma_gemm_f16_kernel<128, 1><<<NB_GEMM, 256, SM_F>>>(nullptr, wf_dev + 1 * 16384);
    agg_bn_kernel<<<NB_AGG, 256>>>(b1, g1, be1, m1, v1);
    mma_gemm_f16_kernel<128, 1><<<NB_GEMM, 256, SM_F>>>(nullptr, wf_dev + 2 * 16384);
    agg_bn_kernel<<<NB_AGG, 256>>>(b2, g2, be2, m2, v2);

    mlp_head_kernel<<<NB_GEMM, 256, SM_H>>>(bm1, bm2, wf_dev + 3 * 16384,
                                            wf_dev + 4 * 16384, out);
}

// round 15
// speedup vs baseline: 1.0416x; 1.0416x over previous
#include <cuda_runtime.h>
#include <cuda_fp16.h>
#include <cstdint>

#define N_NODES 50000
#define N_EDGES 800000
#define HID 128
#define OUTD 64
#define BN_EPS 1e-5f

// ---------------- scratch (device globals: allocation-free) ----------------
__device__ int   g_cnt[N_NODES];
__device__ int   g_rank[N_EDGES];
__device__ int   g_rowptr[N_NODES + 1];
__device__ __align__(16) int2 g_edge[N_EDGES];      // {src, dinv[src] bits} CSR-ordered
__device__ float g_dinv[N_NODES];
__device__ __align__(16) __half g_hp16[(size_t)N_NODES * HID];   // X@W (UNSCALED), fp16
__device__ __align__(16) __half g_act16[(size_t)N_NODES * HID];  // post agg+BN+ReLU, fp16
__device__ __align__(16) __half g_wf16[5 * 16384];  // fp16 weights, n-major [n][128] (slots 1-4 used)

// ---------------- CSR build ----------------
__global__ void hist_kernel(const int* __restrict__ dst) {
    int e = blockIdx.x * blockDim.x + threadIdx.x;
    if (e < N_EDGES) g_rank[e] = atomicAdd(&g_cnt[dst[e]], 1);
}
__global__ void scan_dinv_kernel() {
    __shared__ int warp_sums[32];
    __shared__ int carry_sh;
    const int lane = threadIdx.x & 31, wid = threadIdx.x >> 5;
    if (threadIdx.x == 0) carry_sh = 0;
    __syncthreads();
    for (int base = 0; base < N_NODES; base += 8192) {
        const int c = carry_sh;
        const int idx0 = base + (int)threadIdx.x * 8;
        int v[8];
        if (idx0 + 8 <= N_NODES) {
            int4 a = *reinterpret_cast<const int4*>(g_cnt + idx0);
            int4 b = *reinterpret_cast<const int4*>(g_cnt + idx0 + 4);
            v[0] = a.x; v[1] = a.y; v[2] = a.z; v[3] = a.w;
            v[4] = b.x; v[5] = b.y; v[6] = b.z; v[7] = b.w;
        } else {
#pragma unroll
            for (int j = 0; j < 8; j++) v[j] = (idx0 + j < N_NODES) ? g_cnt[idx0 + j] : 0;
        }
        int p[8];
        p[0] = v[0];
#pragma unroll
        for (int j = 1; j < 8; j++) p[j] = p[j - 1] + v[j];
#pragma unroll
        for (int j = 0; j < 8; j++)
            if (idx0 + j < N_NODES) g_dinv[idx0 + j] = rsqrtf(1.0f + (float)v[j]);
        const int tot = p[7];
        int x = tot;
#pragma unroll
        for (int o = 1; o < 32; o <<= 1) {
            int y = __shfl_up_sync(0xffffffffu, x, o);
            if (lane >= o) x += y;
        }
        if (lane == 31) warp_sums[wid] = x;
        __syncthreads();
        if (wid == 0) {
            int s = warp_sums[lane];
#pragma unroll
            for (int o = 1; o < 32; o <<= 1) {
                int y = __shfl_up_sync(0xffffffffu, s, o);
                if (lane >= o) s += y;
            }
            warp_sums[lane] = s;
        }
        __syncthreads();
        const int basep = c + (wid > 0 ? warp_sums[wid - 1] : 0) + (x - tot);
#pragma unroll
        for (int j = 0; j < 8; j++)
            if (idx0 + j < N_NODES) g_rowptr[idx0 + j + 1] = basep + p[j];
        __syncthreads();
        if (threadIdx.x == 0) carry_sh = c + warp_sums[31];
        __syncthreads();
    }
    if (threadIdx.x == 0) g_rowptr[0] = 0;
}
__global__ void fill_csr_kernel(const int* __restrict__ src, const int* __restrict__ dst) {
    int e = blockIdx.x * blockDim.x + threadIdx.x;
    if (e < N_EDGES) {
        int s = src[e];
        int p = g_rowptr[dst[e]] + g_rank[e];
        g_edge[p] = make_int2(s, __float_as_int(g_dinv[s]));
    }
}

// ---------------- helpers ----------------
__device__ __forceinline__ void mma16816_f16(float* d, const uint32_t* a, const uint32_t* b) {
    asm volatile(
        "mma.sync.aligned.m16n8k16.row.col.f32.f16.f16.f32 "
        "{%0,%1,%2,%3}, {%4,%5,%6,%7}, {%8,%9}, {%0,%1,%2,%3};"
        : "+f"(d[0]), "+f"(d[1]), "+f"(d[2]), "+f"(d[3])
        : "r"(a[0]), "r"(a[1]), "r"(a[2]), "r"(a[3]), "r"(b[0]), "r"(b[1]));
}

// ---- weight prep: slots 1-4 (W1,W2,Wm1,Wm2) fp16, n-major [n][128] ----
// (W0 is converted inline by gemm0 — keeps prep_w off the critical path)
__global__ void prep_w_kernel(const float* __restrict__ W1, const float* __restrict__ W2,
                              const float* __restrict__ Wm1, const float* __restrict__ Wm2) {
    int idx = blockIdx.x * blockDim.x + threadIdx.x;
    int slot = 1 + (idx >> 14), i = idx & 16383;
    if (slot > 4) return;
    const float* W;
    int K, NC;
    if (slot == 1) { W = W1; K = 128; NC = 128; }
    else if (slot == 2) { W = W2; K = 128; NC = 128; }
    else if (slot == 3) { W = Wm1; K = 128; NC = 128; }
    else { W = Wm2; K = 128; NC = 64; }
    if (i >= K * NC) return;
    int k = i / NC, n = i % NC;
    g_wf16[slot * 16384 + n * 128 + k] = __float2half_rn(W[i]);
}

// ---------------- GEMM0 (fp16 MMA): g_hp16 = x[128x64] @ W0, W0 fp32 inline-converted
__global__ __launch_bounds__(256) void gemm0_kernel(const float* __restrict__ X,
                                                    const float* __restrict__ W0) {
    constexpr int LDA = 72;
    extern __shared__ __align__(16) char smem[];
    __half* As = (__half*)smem;                // [128][72]
    __half* Bs = As + 128 * LDA;               // [128][72]

    const int tid = threadIdx.x, wid = tid >> 5, lane = tid & 31;
    const int row0 = blockIdx.x * 128;
    const int m0 = (wid >> 1) * 32, n0 = (wid & 1) * 64;
    const int gid = lane >> 2, tid4 = lane & 3;

    // A fill: x fp32 -> fp16
#pragma unroll
    for (int it = 0; it < 8; it++) {
        int i = tid + it * 256;
        int r = i >> 4, q = (i & 15) * 4;
        uint2 u = make_uint2(0u, 0u);
        if (row0 + r < N_NODES) {
            float4 v = *reinterpret_cast<const float4*>(X + (size_t)(row0 + r) * 64 + q);
            __half2 p0 = __floats2half2_rn(v.x, v.y);
            __half2 p1 = __floats2half2_rn(v.z, v.w);
            u = make_uint2(*reinterpret_cast<uint32_t*>(&p0), *reinterpret_cast<uint32_t*>(&p1));
        }
        *reinterpret_cast<uint2*>(As + r * LDA + q) = u;
    }
    // B fill: W0[k][n] fp32 -> Bs[n][k] fp16 (transpose + convert, L2-resident)
#pragma unroll
    for (int it = 0; it < 8; it++) {
        int i = tid + it * 256;                 // 2048 quads
        int n = i >> 4, q = (i & 15) * 4;       // k-quad in [0,64)
        float w0 = W0[(size_t)(q + 0) * 128 + n];
        float w1 = W0[(size_t)(q + 1) * 128 + n];
        float w2 = W0[(size_t)(q + 2) * 128 + n];
        float w3 = W0[(size_t)(q + 3) * 128 + n];
        __half2 p0 = __floats2half2_rn(w0, w1);
        __half2 p1 = __floats2half2_rn(w2, w3);
        *reinterpret_cast<uint2*>(Bs + n * LDA + q) =
            make_uint2(*reinterpret_cast<uint32_t*>(&p0), *reinterpret_cast<uint32_t*>(&p1));
    }
    __syncthreads();

    float acc[2][8][4];
#pragma unroll
    for (int mi = 0; mi < 2; mi++)
#pragma unroll
        for (int ni = 0; ni < 8; ni++)
#pragma unroll
            for (int j = 0; j < 4; j++) acc[mi][ni][j] = 0.f;

#pragma unroll
    for (int k16 = 0; k16 < 64; k16 += 16) {
        uint32_t bh[8][2];
#pragma unroll
        for (int ni = 0; ni < 8; ni++) {
            const __half* bp = Bs + (n0 + ni * 8 + gid) * LDA + k16 + tid4 * 2;
            bh[ni][0] = *reinterpret_cast<const uint32_t*>(bp);
            bh[ni][1] = *reinterpret_cast<const uint32_t*>(bp + 8);
        }
#pragma unroll
        for (int mi = 0; mi < 2; mi++) {
            const int r = m0 + mi * 16 + gid, c = k16 + tid4 * 2;
            uint32_t ah[4];
            ah[0] = *reinterpret_cast<const uint32_t*>(As + r * LDA + c);
            ah[1] = *reinterpret_cast<const uint32_t*>(As + (r + 8) * LDA + c);
            ah[2] = *reinterpret_cast<const uint32_t*>(As + r * LDA + c + 8);
            ah[3] = *reinterpret_cast<const uint32_t*>(As + (r + 8) * LDA + c + 8);
#pragma unroll
            for (int ni = 0; ni < 8; ni++) mma16816_f16(acc[mi][ni], ah, bh[ni]);
        }
    }

#pragma unroll
    for (int mi = 0; mi < 2; mi++)
#pragma unroll
        for (int rr = 0; rr < 2; rr++) {
            int r = row0 + m0 + mi * 16 + gid + rr * 8;
            if (r < N_NODES) {
#pragma unroll
                for (int ni = 0; ni < 8; ni++) {
                    int cn = n0 + ni * 8 + tid4 * 2;
                    __half2 o = __floats2half2_rn(acc[mi][ni][rr * 2],
                                                  acc[mi][ni][rr * 2 + 1]);
                    *reinterpret_cast<__half2*>(g_hp16 + (size_t)r * HID + cn) = o;
                }
            }
        }
}

// ---------------- fp16 HMMA GEMM (K=128): g_hp16 = g_act16 @ W ---------------------
__global__ __launch_bounds__(256) void mma_gemm_f16_kernel(const __half* __restrict__ wf) {
    constexpr int LDA = 72;
    extern __shared__ __align__(16) char smem[];
    __half* As = (__half*)smem;                // [128][72]
    __half* Bs = As + 128 * LDA;               // [128][72]

    const int tid = threadIdx.x, wid = tid >> 5, lane = tid & 31;
    const int row0 = blockIdx.x * 128;
    const int m0 = (wid >> 1) * 32, n0 = (wid & 1) * 64;
    const int gid = lane >> 2, tid4 = lane & 3;

    float acc[2][8][4];
#pragma unroll
    for (int mi = 0; mi < 2; mi++)
#pragma unroll
        for (int ni = 0; ni < 8; ni++)
#pragma unroll
            for (int j = 0; j < 4; j++) acc[mi][ni][j] = 0.f;

    for (int kc = 0; kc < 128; kc += 64) {
        if (kc) __syncthreads();
#pragma unroll
        for (int it = 0; it < 8; it++) {
            int i = tid + it * 256;
            int r = i >> 4, q = (i & 15) * 4;
            uint2 u = make_uint2(0u, 0u);
            if (row0 + r < N_NODES)
                u = *reinterpret_cast<const uint2*>(
                    g_act16 + (size_t)(row0 + r) * HID + kc + q);
            *reinterpret_cast<uint2*>(As + r * LDA + q) = u;
        }
#pragma unroll
        for (int it = 0; it < 8; it++) {
            int i = tid + it * 256;
            int n = i >> 4, q = (i & 15) * 4;
            *reinterpret_cast<uint2*>(Bs + n * LDA + q) =
                *reinterpret_cast<const uint2*>(wf + n * 128 + kc + q);
        }
        __syncthreads();

#pragma unroll
        for (int k16 = 0; k16 < 64; k16 += 16) {
            uint32_t bh[8][2];
#pragma unroll
            for (int ni = 0; ni < 8; ni++) {
                const __half* bp = Bs + (n0 + ni * 8 + gid) * LDA + k16 + tid4 * 2;
                bh[ni][0] = *reinterpret_cast<const uint32_t*>(bp);
                bh[ni][1] = *reinterpret_cast<const uint32_t*>(bp + 8);
            }
#pragma unroll
            for (int mi = 0; mi < 2; mi++) {
                const int r = m0 + mi * 16 + gid, c = k16 + tid4 * 2;
                uint32_t ah[4];
                ah[0] = *reinterpret_cast<const uint32_t*>(As + r * LDA + c);
                ah[1] = *reinterpret_cast<const uint32_t*>(As + (r + 8) * LDA + c);
                ah[2] = *reinterpret_cast<const uint32_t*>(As + r * LDA + c + 8);
                ah[3] = *reinterpret_cast<const uint32_t*>(As + (r + 8) * LDA + c + 8);
#pragma unroll
                for (int ni = 0; ni < 8; ni++) mma16816_f16(acc[mi][ni], ah, bh[ni]);
            }
        }
    }

#pragma unroll
    for (int mi = 0; mi < 2; mi++)
#pragma unroll
        for (int rr = 0; rr < 2; rr++) {
            int r = row0 + m0 + mi * 16 + gid + rr * 8;
            if (r < N_NODES) {
#pragma unroll
                for (int ni = 0; ni < 8; ni++) {
                    int cn = n0 + ni * 8 + tid4 * 2;
                    __half2 o = __floats2half2_rn(acc[mi][ni][rr * 2],
                                                  acc[mi][ni][rr * 2 + 1]);
                    *reinterpret_cast<__half2*>(g_hp16 + (size_t)r * HID + cn) = o;
                }
            }
        }
}

// ---- CSR aggregation (8-batch + serial tail — proven round-13 form) --------------
__global__ __launch_bounds__(256) void agg_bn_kernel(const float* __restrict__ bias,
                                                     const float* __restrict__ gam,
                                                     const float* __restrict__ bet,
                                                     const float* __restrict__ mu,
                                                     const float* __restrict__ var) {
    int n = (blockIdx.x * 256 + threadIdx.x) >> 5;
    int lane = threadIdx.x & 31;
    if (n >= N_NODES) return;

    const __half* hp = g_hp16;
    const float dn = g_dinv[n];
    float4 acc;
    {
        uint2 u = *reinterpret_cast<const uint2*>(hp + (size_t)n * HID + lane * 4);
        float2 f0 = __half22float2(*reinterpret_cast<__half2*>(&u.x));
        float2 f1 = __half22float2(*reinterpret_cast<__half2*>(&u.y));
        acc = make_float4(dn * f0.x, dn * f0.y, dn * f1.x, dn * f1.y);
    }

    int e = g_rowptr[n];
    const int e1 = g_rowptr[n + 1];
    for (; e + 8 <= e1; e += 8) {
        int2 ec[8];
#pragma unroll
        for (int j = 0; j < 8; j++) ec[j] = g_edge[e + j];
        uint2 u[8];
#pragma unroll
        for (int j = 0; j < 8; j++)
            u[j] = *reinterpret_cast<const uint2*>(hp + (size_t)ec[j].x * HID + lane * 4);
#pragma unroll
        for (int j = 0; j < 8; j++) {
            float c = __int_as_float(ec[j].y);
            float2 f0 = __half22float2(*reinterpret_cast<__half2*>(&u[j].x));
            float2 f1 = __half22float2(*reinterpret_cast<__half2*>(&u[j].y));
            acc.x = fmaf(c, f0.x, acc.x);
            acc.y = fmaf(c, f0.y, acc.y);
            acc.z = fmaf(c, f1.x, acc.z);
            acc.w = fmaf(c, f1.y, acc.w);
        }
    }
    for (; e < e1; e++) {
        int2 ec = g_edge[e];
        float c = __int_as_float(ec.y);
        uint2 u = *reinterpret_cast<const uint2*>(hp + (size_t)ec.x * HID + lane * 4);
        float2 f0 = __half22float2(*reinterpret_cast<__half2*>(&u.x));
        float2 f1 = __half22float2(*reinterpret_cast<__half2*>(&u.y));
        acc.x = fmaf(c, f0.x, acc.x);
        acc.y = fmaf(c, f0.y, acc.y);
        acc.z = fmaf(c, f1.x, acc.z);
        acc.w = fmaf(c, f1.y, acc.w);
    }

    float4 gg = reinterpret_cast<const float4*>(gam)[lane];
    float4 vv = reinterpret_cast<const float4*>(var)[lane];
    float4 mm = reinterpret_cast<const float4*>(mu)[lane];
    float4 be = reinterpret_cast<const float4*>(bet)[lane];
    float4 bb = reinterpret_cast<const float4*>(bias)[lane];
    float4 o;
    {
        float s;
        s = gg.x * rsqrtf(vv.x + BN_EPS); o.x = fmaxf((dn * acc.x + bb.x - mm.x) * s + be.x, 0.f);
        s = gg.y * rsqrtf(vv.y + BN_EPS); o.y = fmaxf((dn * acc.y + bb.y - mm.y) * s + be.y, 0.f);
        s = gg.z * rsqrtf(vv.z + BN_EPS); o.z = fmaxf((dn * acc.z + bb.z - mm.z) * s + be.z, 0.f);
        s = gg.w * rsqrtf(vv.w + BN_EPS); o.w = fmaxf((dn * acc.w + bb.w - mm.w) * s + be.w, 0.f);
    }
    __half2 h0 = __floats2half2_rn(o.x, o.y);
    __half2 h1 = __floats2half2_rn(o.z, o.w);
    *reinterpret_cast<uint2*>(g_act16 + (size_t)n * HID + lane * 4) =
        make_uint2(*reinterpret_cast<uint32_t*>(&h0), *reinterpret_cast<uint32_t*>(&h1));
}

// ---------------- fused MLP head: both stages fp16 --------------------------------
__global__ __launch_bounds__(256) void mlp_head_kernel(const float* __restrict__ bm1,
                                                       const float* __restrict__ bm2,
                                                       const __half* __restrict__ w1f,
                                                       const __half* __restrict__ w2f,
                                                       float* __restrict__ outext) {
    constexpr int LDA = 136, LDB = 72;
    extern __shared__ __align__(16) char smem[];
    __half* As16 = (__half*)smem;                      // [128][136] A / later H
    __half* Bs16 = (__half*)(smem + 34816);            // [128][136] Wm1
    __half* B2 = (__half*)(smem + 69632);              // [64][72] Wm2 chunk

    const int tid = threadIdx.x, wid = tid >> 5, lane = tid & 31;
    const int row0 = blockIdx.x * 128;
    const int gid = lane >> 2, tid4 = lane & 3;

#pragma unroll
    for (int it = 0; it < 8; it++) {
        int i = tid + it * 256;
        int r = i >> 4, q = (i & 15) * 8;
        uint4 u = make_uint4(0u, 0u, 0u, 0u);
        if (row0 + r < N_NODES)
            u = *reinterpret_cast<const uint4*>(g_act16 + (size_t)(row0 + r) * HID + q);
        *reinterpret_cast<uint4*>(As16 + r * LDA + q) = u;
    }
#pragma unroll
    for (int it = 0; it < 8; it++) {
        int i = tid + it * 256;
        int n = i >> 4, q = (i & 15) * 8;
        *reinterpret_cast<uint4*>(Bs16 + n * LDA + q) =
            *reinterpret_cast<const uint4*>(w1f + n * 128 + q);
    }
    __syncthreads();

    const int m0 = (wid >> 1) * 32, n0 = (wid & 1) * 64;
    float acc[2][8][4];
#pragma unroll
    for (int mi = 0; mi < 2; mi++)
#pragma unroll
        for (int ni = 0; ni < 8; ni++)
#pragma unroll
            for (int j = 0; j < 4; j++) acc[mi][ni][j] = 0.f;

#pragma unroll
    for (int k16 = 0; k16 < 128; k16 += 16) {
        uint32_t bh[8][2];
#pragma unroll
        for (int ni = 0; ni < 8; ni++) {
            const __half* bp = Bs16 + (n0 + ni * 8 + gid) * LDA + k16 + tid4 * 2;
            bh[ni][0] = *reinterpret_cast<const uint32_t*>(bp);
            bh[ni][1] = *reinterpret_cast<const uint32_t*>(bp + 8);
        }
#pragma unroll
        for (int mi = 0; mi < 2; mi++) {
            const int r = m0 + mi * 16 + gid, c = k16 + tid4 * 2;
            uint32_t ah[4];
            ah[0] = *reinterpret_cast<const uint32_t*>(As16 + r * LDA + c);
            ah[1] = *reinterpret_cast<const uint32_t*>(As16 + (r + 8) * LDA + c);
            ah[2] = *reinterpret_cast<const uint32_t*>(As16 + r * LDA + c + 8);
            ah[3] = *reinterpret_cast<const uint32_t*>(As16 + (r + 8) * LDA + c + 8);
#pragma unroll
            for (int ni = 0; ni < 8; ni++) mma16816_f16(acc[mi][ni], ah, bh[ni]);
        }
    }
    __syncthreads();

#pragma unroll
    for (int mi = 0; mi < 2; mi++)
#pragma unroll
        for (int rr = 0; rr < 2; rr++) {
            int lr = m0 + mi * 16 + gid + rr * 8;
#pragma unroll
            for (int ni = 0; ni < 8; ni++) {
                int cn = n0 + ni * 8 + tid4 * 2;
                float2 bb = *reinterpret_cast<const float2*>(bm1 + cn);
                __half2 h = __floats2half2_rn(fmaxf(acc[mi][ni][rr * 2] + bb.x, 0.f),
                                              fmaxf(acc[mi][ni][rr * 2 + 1] + bb.y, 0.f));
                *reinterpret_cast<__half2*>(As16 + lr * LDA + cn) = h;
            }
        }
    __syncthreads();

    const int n02 = (wid & 1) * 32;
    float acc2[2][4][4];
#pragma unroll
    for (int mi = 0; mi < 2; mi++)
#pragma unroll
        for (int ni = 0; ni < 4; ni++)
#pragma unroll
            for (int j = 0; j < 4; j++) acc2[mi][ni][j] = 0.f;

    for (int kc = 0; kc < 128; kc += 64) {
        if (kc) __syncthreads();
#pragma unroll
        for (int it = 0; it < 4; it++) {
            int i = tid + it * 256;
            int n = i >> 4, q = (i & 15) * 4;
            *reinterpret_cast<uint2*>(B2 + n * LDB + q) =
                *reinterpret_cast<const uint2*>(w2f + n * 128 + kc + q);
        }
        __syncthreads();
#pragma unroll
        for (int k16 = 0; k16 < 64; k16 += 16) {
            uint32_t bh[4][2];
#pragma unroll
            for (int ni = 0; ni < 4; ni++) {
                const __half* bp = B2 + (n02 + ni * 8 + gid) * LDB + k16 + tid4 * 2;
                bh[ni][0] = *reinterpret_cast<const uint32_t*>(bp);
                bh[ni][1] = *reinterpret_cast<const uint32_t*>(bp + 8);
            }
#pragma unroll
            for (int mi = 0; mi < 2; mi++) {
                const int r = m0 + mi * 16 + gid, c = kc + k16 + tid4 * 2;
                uint32_t ah[4];
                ah[0] = *reinterpret_cast<const uint32_t*>(As16 + r * LDA + c);
                ah[1] = *reinterpret_cast<const uint32_t*>(As16 + (r + 8) * LDA + c);
                ah[2] = *reinterpret_cast<const uint32_t*>(As16 + r * LDA + c + 8);
                ah[3] = *reinterpret_cast<const uint32_t*>(As16 + (r + 8) * LDA + c + 8);
#pragma unroll
                for (int ni = 0; ni < 4; ni++) mma16816_f16(acc2[mi][ni], ah, bh[ni]);
            }
        }
    }

#pragma unroll
    for (int mi = 0; mi < 2; mi++)
#pragma unroll
        for (int rr = 0; rr < 2; rr++) {
            int r = row0 + m0 + mi * 16 + gid + rr * 8;
            if (r < N_NODES) {
#pragma unroll
                for (int ni = 0; ni < 4; ni++) {
                    int cn = n02 + ni * 8 + tid4 * 2;
                    float2 bb = *reinterpret_cast<const float2*>(bm2 + cn);
                    float2 o = make_float2(acc2[mi][ni][rr * 2] + bb.x,
                                           acc2[mi][ni][rr * 2 + 1] + bb.y);
                    *reinterpret_cast<float2*>(outext + (size_t)r * OUTD + cn) = o;
                }
            }
        }
}

// ---------------- launch ----------------
extern "C" void kernel_launch(void* const* d_in, const int* in_sizes, int n_in,
                              void* d_out, int out_size) {
    (void)in_sizes; (void)n_in; (void)out_size;
    const float* x   = (const float*)d_in[0];
    const int*   src = (const int*)d_in[1];
    const int*   dst = (const int*)d_in[2];
    const float* W0 = (const float*)d_in[3],  *b0 = (const float*)d_in[4];
    const float* g0 = (const float*)d_in[5],  *be0 = (const float*)d_in[6];
    const float* m0 = (const float*)d_in[7],  *v0 = (const float*)d_in[8];
    const float* W1 = (const float*)d_in[9],  *b1 = (const float*)d_in[10];
    const float* g1 = (const float*)d_in[11], *be1 = (const float*)d_in[12];
    const float* m1 = (const float*)d_in[13], *v1 = (const float*)d_in[14];
    const float* W2 = (const float*)d_in[15], *b2 = (const float*)d_in[16];
    const float* g2 = (const float*)d_in[17], *be2 = (const float*)d_in[18];
    const float* m2 = (const float*)d_in[19], *v2 = (const float*)d_in[20];
    const float* Wm1 = (const float*)d_in[21], *bm1 = (const float*)d_in[22];
    const float* Wm2 = (const float*)d_in[23], *bm2 = (const float*)d_in[24];
    float* out = (float*)d_out;

    const int NB_EDGE = (N_EDGES + 255) / 256;
    const int NB_GEMM = (N_NODES + 127) / 128;
    const int NB_AGG  = (N_NODES + 7) / 8;

    constexpr int SM_F = (128 * 72 + 128 * 72) * 2;     // 36864
    constexpr int SM_H = 69632 + 64 * 72 * 2;           // 78848

    cudaFuncSetAttribute(gemm0_kernel, cudaFuncAttributeMaxDynamicSharedMemorySize, SM_F);
    cudaFuncSetAttribute(mma_gemm_f16_kernel, cudaFuncAttributeMaxDynamicSharedMemorySize, SM_F);
    cudaFuncSetAttribute(mlp_head_kernel, cudaFuncAttributeMaxDynamicSharedMemorySize, SM_H);

    __half* wf_dev = nullptr;
    int* cnt_dev = nullptr;
    cudaGetSymbolAddress((void**)&wf_dev, g_wf16);
    cudaGetSymbolAddress((void**)&cnt_dev, g_cnt);

    // side stream: weight prep (slots 1-4) + CSR build, all covered by the join
    static cudaStream_t s2 = nullptr;
    static cudaEvent_t evFork = nullptr, evJoin = nullptr;
    if (s2 == nullptr) {
        cudaStreamCreateWithFlags(&s2, cudaStreamNonBlocking);
        cudaEventCreateWithFlags(&evFork, cudaEventDisableTiming);
        cudaEventCreateWithFlags(&evJoin, cudaEventDisableTiming);
    }

    cudaEventRecord(evFork, 0);
    cudaStreamWaitEvent(s2, evFork, 0);
    prep_w_kernel<<<(4 * 16384 + 255) / 256, 256, 0, s2>>>(W1, W2, Wm1, Wm2);
    cudaMemsetAsync(cnt_dev, 0, N_NODES * sizeof(int), s2);
    hist_kernel<<<NB_EDGE, 256, 0, s2>>>(dst);
    scan_dinv_kernel<<<1, 1024, 0, s2>>>();
    fill_csr_kernel<<<NB_EDGE, 256, 0, s2>>>(src, dst);
    cudaEventRecord(evJoin, s2);

    // main stream: layer-0 GEMM starts immediately (W0 converted inline)
    gemm0_kernel<<<NB_GEMM, 256, SM_F>>>(x, W0);

    cudaStreamWaitEvent(0, evJoin, 0);

    agg_bn_kernel<<<NB_AGG, 256>>>(b0, g0, be0, m0, v0);
    mma_gemm_f16_kernel<<<NB_GEMM, 256, SM_F>>>(wf_dev + 1 * 16384);
    agg_bn_kernel<<<NB_AGG, 256>>>(b1, g1, be1, m1, v1);
    mma_gemm_f16_kernel<<<NB_GEMM, 256, SM_F>>>(wf_dev + 2 * 16384);
    agg_bn_kernel<<<NB_AGG, 256>>>(b2, g2, be2, m2, v2);

    mlp_head_kernel<<<NB_GEMM, 256, SM_H>>>(bm1, bm2, wf_dev + 3 * 16384,
                                            wf_dev + 4 * 16384, out);
}

// round 16
// speedup vs baseline: 1.0875x; 1.0441x over previous
#include <cuda_runtime.h>
#include <cuda_fp16.h>
#include <cstdint>

#define N_NODES 50000
#define N_EDGES 800000
#define HID 128
#define OUTD 64
#define BN_EPS 1e-5f

// ---------------- scratch (device globals: allocation-free) ----------------
// g_cnt is zero-initialized (BSS) and re-zeroed by fill_csr_kernel each call.
__device__ int   g_cnt[N_NODES];
__device__ int   g_rank[N_EDGES];
__device__ int   g_rowptr[N_NODES + 1];
__device__ __align__(16) int2 g_edge[N_EDGES];      // {src, dinv[src] bits} CSR-ordered
__device__ float g_dinv[N_NODES];
__device__ __align__(16) __half g_hp16[(size_t)N_NODES * HID];   // X@W (UNSCALED), fp16
__device__ __align__(16) __half g_act16[(size_t)N_NODES * HID];  // post agg+BN+ReLU, fp16
__device__ __align__(16) __half g_wf16[5 * 16384];  // fp16 weights, n-major [n][128]

// ---------------- CSR build ----------------
__global__ void hist_kernel(const int* __restrict__ dst) {
    int e = blockIdx.x * blockDim.x + threadIdx.x;
    if (e < N_EDGES) g_rank[e] = atomicAdd(&g_cnt[dst[e]], 1);
}
__global__ void scan_dinv_kernel() {
    __shared__ int warp_sums[32];
    __shared__ int carry_sh;
    const int lane = threadIdx.x & 31, wid = threadIdx.x >> 5;
    if (threadIdx.x == 0) carry_sh = 0;
    __syncthreads();
    for (int base = 0; base < N_NODES; base += 8192) {
        const int c = carry_sh;
        const int idx0 = base + (int)threadIdx.x * 8;
        int v[8];
        if (idx0 + 8 <= N_NODES) {
            int4 a = *reinterpret_cast<const int4*>(g_cnt + idx0);
            int4 b = *reinterpret_cast<const int4*>(g_cnt + idx0 + 4);
            v[0] = a.x; v[1] = a.y; v[2] = a.z; v[3] = a.w;
            v[4] = b.x; v[5] = b.y; v[6] = b.z; v[7] = b.w;
        } else {
#pragma unroll
            for (int j = 0; j < 8; j++) v[j] = (idx0 + j < N_NODES) ? g_cnt[idx0 + j] : 0;
        }
        int p[8];
        p[0] = v[0];
#pragma unroll
        for (int j = 1; j < 8; j++) p[j] = p[j - 1] + v[j];
#pragma unroll
        for (int j = 0; j < 8; j++)
            if (idx0 + j < N_NODES) g_dinv[idx0 + j] = rsqrtf(1.0f + (float)v[j]);
        const int tot = p[7];
        int x = tot;
#pragma unroll
        for (int o = 1; o < 32; o <<= 1) {
            int y = __shfl_up_sync(0xffffffffu, x, o);
            if (lane >= o) x += y;
        }
        if (lane == 31) warp_sums[wid] = x;
        __syncthreads();
        if (wid == 0) {
            int s = warp_sums[lane];
#pragma unroll
            for (int o = 1; o < 32; o <<= 1) {
                int y = __shfl_up_sync(0xffffffffu, s, o);
                if (lane >= o) s += y;
            }
            warp_sums[lane] = s;
        }
        __syncthreads();
        const int basep = c + (wid > 0 ? warp_sums[wid - 1] : 0) + (x - tot);
#pragma unroll
        for (int j = 0; j < 8; j++)
            if (idx0 + j < N_NODES) g_rowptr[idx0 + j + 1] = basep + p[j];
        __syncthreads();
        if (threadIdx.x == 0) carry_sh = c + warp_sums[31];
        __syncthreads();
    }
    if (threadIdx.x == 0) g_rowptr[0] = 0;
}
// also re-zeroes g_cnt (consumed by scan above; next call's hist needs zeros)
__global__ void fill_csr_kernel(const int* __restrict__ src, const int* __restrict__ dst) {
    int e = blockIdx.x * blockDim.x + threadIdx.x;
    if (e < N_NODES) g_cnt[e] = 0;
    if (e < N_EDGES) {
        int s = src[e];
        int p = g_rowptr[dst[e]] + g_rank[e];
        g_edge[p] = make_int2(s, __float_as_int(g_dinv[s]));
    }
}

// ---------------- helpers ----------------
__device__ __forceinline__ void mma16816_f16(float* d, const uint32_t* a, const uint32_t* b) {
    asm volatile(
        "mma.sync.aligned.m16n8k16.row.col.f32.f16.f16.f32 "
        "{%0,%1,%2,%3}, {%4,%5,%6,%7}, {%8,%9}, {%0,%1,%2,%3};"
        : "+f"(d[0]), "+f"(d[1]), "+f"(d[2]), "+f"(d[3])
        : "r"(a[0]), "r"(a[1]), "r"(a[2]), "r"(a[3]), "r"(b[0]), "r"(b[1]));
}

// ---- weight prep: all 5 slots fp16, n-major [n][128] ----
__global__ void prep_w_kernel(const float* __restrict__ W0, const float* __restrict__ W1,
                              const float* __restrict__ W2, const float* __restrict__ Wm1,
                              const float* __restrict__ Wm2) {
    int idx = blockIdx.x * blockDim.x + threadIdx.x;
    int slot = idx >> 14, i = idx & 16383;
    if (slot >= 5) return;
    const float* W;
    int K, NC;
    if (slot == 0) { W = W0; K = 64; NC = 128; }
    else if (slot == 1) { W = W1; K = 128; NC = 128; }
    else if (slot == 2) { W = W2; K = 128; NC = 128; }
    else if (slot == 3) { W = Wm1; K = 128; NC = 128; }
    else { W = Wm2; K = 128; NC = 64; }
    if (i >= K * NC) return;
    int k = i / NC, n = i % NC;
    g_wf16[slot * 16384 + n * 128 + k] = __float2half_rn(W[i]);
}

// ---------------- fp16 HMMA GEMM: g_hp16 = X[128 x K] @ W  (unscaled) -------------
// SRCSEL: 0 = external fp32 X (K=64), 1 = g_act16 fp16 (K=128)
template <int K, int SRCSEL>
__global__ __launch_bounds__(256) void mma_gemm_f16_kernel(const float* __restrict__ Xext,
                                                           const __half* __restrict__ wf) {
    constexpr int LDA = 72;
    extern __shared__ __align__(16) char smem[];
    __half* As = (__half*)smem;                // [128][72]
    __half* Bs = As + 128 * LDA;               // [128][72]

    const int tid = threadIdx.x, wid = tid >> 5, lane = tid & 31;
    const int row0 = blockIdx.x * 128;
    const int m0 = (wid >> 1) * 32, n0 = (wid & 1) * 64;
    const int gid = lane >> 2, tid4 = lane & 3;

    float acc[2][8][4];
#pragma unroll
    for (int mi = 0; mi < 2; mi++)
#pragma unroll
        for (int ni = 0; ni < 8; ni++)
#pragma unroll
            for (int j = 0; j < 4; j++) acc[mi][ni][j] = 0.f;

    for (int kc = 0; kc < K; kc += 64) {
        if (kc) __syncthreads();
        // A chunk fill
#pragma unroll
        for (int it = 0; it < 8; it++) {
            int i = tid + it * 256;
            int r = i >> 4, q = (i & 15) * 4;
            uint2 u = make_uint2(0u, 0u);
            if (row0 + r < N_NODES) {
                if (SRCSEL == 0) {
                    float4 v = *reinterpret_cast<const float4*>(
                        Xext + (size_t)(row0 + r) * K + kc + q);
                    __half2 p0 = __floats2half2_rn(v.x, v.y);
                    __half2 p1 = __floats2half2_rn(v.z, v.w);
                    u = make_uint2(*reinterpret_cast<uint32_t*>(&p0),
                                   *reinterpret_cast<uint32_t*>(&p1));
                } else {
                    u = *reinterpret_cast<const uint2*>(
                        g_act16 + (size_t)(row0 + r) * HID + kc + q);
                }
            }
            *reinterpret_cast<uint2*>(As + r * LDA + q) = u;
        }
        // B chunk fill: pure copy from pre-converted fp16 weights
#pragma unroll
        for (int it = 0; it < 8; it++) {
            int i = tid + it * 256;
            int n = i >> 4, q = (i & 15) * 4;
            *reinterpret_cast<uint2*>(Bs + n * LDA + q) =
                *reinterpret_cast<const uint2*>(wf + n * 128 + kc + q);
        }
        __syncthreads();

#pragma unroll
        for (int k16 = 0; k16 < 64; k16 += 16) {
            uint32_t bh[8][2];
#pragma unroll
            for (int ni = 0; ni < 8; ni++) {
                const __half* bp = Bs + (n0 + ni * 8 + gid) * LDA + k16 + tid4 * 2;
                bh[ni][0] = *reinterpret_cast<const uint32_t*>(bp);
                bh[ni][1] = *reinterpret_cast<const uint32_t*>(bp + 8);
            }
#pragma unroll
            for (int mi = 0; mi < 2; mi++) {
                const int r = m0 + mi * 16 + gid, c = k16 + tid4 * 2;
                uint32_t ah[4];
                ah[0] = *reinterpret_cast<const uint32_t*>(As + r * LDA + c);
                ah[1] = *reinterpret_cast<const uint32_t*>(As + (r + 8) * LDA + c);
                ah[2] = *reinterpret_cast<const uint32_t*>(As + r * LDA + c + 8);
                ah[3] = *reinterpret_cast<const uint32_t*>(As + (r + 8) * LDA + c + 8);
#pragma unroll
                for (int ni = 0; ni < 8; ni++) mma16816_f16(acc[mi][ni], ah, bh[ni]);
            }
        }
    }

#pragma unroll
    for (int mi = 0; mi < 2; mi++)
#pragma unroll
        for (int rr = 0; rr < 2; rr++) {
            int r = row0 + m0 + mi * 16 + gid + rr * 8;
            if (r < N_NODES) {
#pragma unroll
                for (int ni = 0; ni < 8; ni++) {
                    int cn = n0 + ni * 8 + tid4 * 2;
                    __half2 o = __floats2half2_rn(acc[mi][ni][rr * 2],
                                                  acc[mi][ni][rr * 2 + 1]);
                    *reinterpret_cast<__half2*>(g_hp16 + (size_t)r * HID + cn) = o;
                }
            }
        }
}

// ---- CSR aggregation (8-batch + serial tail) + BN + ReLU -> fp16 act -------------
__global__ __launch_bounds__(256) void agg_bn_kernel(const float* __restrict__ bias,
                                                     const float* __restrict__ gam,
                                                     const float* __restrict__ bet,
                                                     const float* __restrict__ mu,
                                                     const float* __restrict__ var) {
    int n = (blockIdx.x * 256 + threadIdx.x) >> 5;
    int lane = threadIdx.x & 31;
    if (n >= N_NODES) return;

    const __half* hp = g_hp16;
    const float dn = g_dinv[n];
    float4 acc;
    {
        uint2 u = *reinterpret_cast<const uint2*>(hp + (size_t)n * HID + lane * 4);
        float2 f0 = __half22float2(*reinterpret_cast<__half2*>(&u.x));
        float2 f1 = __half22float2(*reinterpret_cast<__half2*>(&u.y));
        acc = make_float4(dn * f0.x, dn * f0.y, dn * f1.x, dn * f1.y);
    }

    int e = g_rowptr[n];
    const int e1 = g_rowptr[n + 1];
    for (; e + 8 <= e1; e += 8) {
        int2 ec[8];
#pragma unroll
        for (int j = 0; j < 8; j++) ec[j] = g_edge[e + j];
        uint2 u[8];
#pragma unroll
        for (int j = 0; j < 8; j++)
            u[j] = *reinterpret_cast<const uint2*>(hp + (size_t)ec[j].x * HID + lane * 4);
#pragma unroll
        for (int j = 0; j < 8; j++) {
            float c = __int_as_float(ec[j].y);
            float2 f0 = __half22float2(*reinterpret_cast<__half2*>(&u[j].x));
            float2 f1 = __half22float2(*reinterpret_cast<__half2*>(&u[j].y));
            acc.x = fmaf(c, f0.x, acc.x);
            acc.y = fmaf(c, f0.y, acc.y);
            acc.z = fmaf(c, f1.x, acc.z);
            acc.w = fmaf(c, f1.y, acc.w);
        }
    }
    for (; e < e1; e++) {
        int2 ec = g_edge[e];
        float c = __int_as_float(ec.y);
        uint2 u = *reinterpret_cast<const uint2*>(hp + (size_t)ec.x * HID + lane * 4);
        float2 f0 = __half22float2(*reinterpret_cast<__half2*>(&u.x));
        float2 f1 = __half22float2(*reinterpret_cast<__half2*>(&u.y));
        acc.x = fmaf(c, f0.x, acc.x);
        acc.y = fmaf(c, f0.y, acc.y);
        acc.z = fmaf(c, f1.x, acc.z);
        acc.w = fmaf(c, f1.y, acc.w);
    }

    float4 gg = reinterpret_cast<const float4*>(gam)[lane];
    float4 vv = reinterpret_cast<const float4*>(var)[lane];
    float4 mm = reinterpret_cast<const float4*>(mu)[lane];
    float4 be = reinterpret_cast<const float4*>(bet)[lane];
    float4 bb = reinterpret_cast<const float4*>(bias)[lane];
    float4 o;
    {
        float s;
        s = gg.x * rsqrtf(vv.x + BN_EPS); o.x = fmaxf((dn * acc.x + bb.x - mm.x) * s + be.x, 0.f);
        s = gg.y * rsqrtf(vv.y + BN_EPS); o.y = fmaxf((dn * acc.y + bb.y - mm.y) * s + be.y, 0.f);
        s = gg.z * rsqrtf(vv.z + BN_EPS); o.z = fmaxf((dn * acc.z + bb.z - mm.z) * s + be.z, 0.f);
        s = gg.w * rsqrtf(vv.w + BN_EPS); o.w = fmaxf((dn * acc.w + bb.w - mm.w) * s + be.w, 0.f);
    }
    __half2 h0 = __floats2half2_rn(o.x, o.y);
    __half2 h1 = __floats2half2_rn(o.z, o.w);
    *reinterpret_cast<uint2*>(g_act16 + (size_t)n * HID + lane * 4) =
        make_uint2(*reinterpret_cast<uint32_t*>(&h0), *reinterpret_cast<uint32_t*>(&h1));
}

// ---------------- fused MLP head: both stages fp16 --------------------------------
__global__ __launch_bounds__(256) void mlp_head_kernel(const float* __restrict__ bm1,
                                                       const float* __restrict__ bm2,
                                                       const __half* __restrict__ w1f,
                                                       const __half* __restrict__ w2f,
                                                       float* __restrict__ outext) {
    constexpr int LDA = 136, LDB = 72;
    extern __shared__ __align__(16) char smem[];
    __half* As16 = (__half*)smem;                      // [128][136] A / later H
    __half* Bs16 = (__half*)(smem + 34816);            // [128][136] Wm1
    __half* B2 = (__half*)(smem + 69632);              // [64][72] Wm2 chunk

    const int tid = threadIdx.x, wid = tid >> 5, lane = tid & 31;
    const int row0 = blockIdx.x * 128;
    const int gid = lane >> 2, tid4 = lane & 3;

#pragma unroll
    for (int it = 0; it < 8; it++) {
        int i = tid + it * 256;
        int r = i >> 4, q = (i & 15) * 8;
        uint4 u = make_uint4(0u, 0u, 0u, 0u);
        if (row0 + r < N_NODES)
            u = *reinterpret_cast<const uint4*>(g_act16 + (size_t)(row0 + r) * HID + q);
        *reinterpret_cast<uint4*>(As16 + r * LDA + q) = u;
    }
#pragma unroll
    for (int it = 0; it < 8; it++) {
        int i = tid + it * 256;
        int n = i >> 4, q = (i & 15) * 8;
        *reinterpret_cast<uint4*>(Bs16 + n * LDA + q) =
            *reinterpret_cast<const uint4*>(w1f + n * 128 + q);
    }
    __syncthreads();

    const int m0 = (wid >> 1) * 32, n0 = (wid & 1) * 64;
    float acc[2][8][4];
#pragma unroll
    for (int mi = 0; mi < 2; mi++)
#pragma unroll
        for (int ni = 0; ni < 8; ni++)
#pragma unroll
            for (int j = 0; j < 4; j++) acc[mi][ni][j] = 0.f;

#pragma unroll
    for (int k16 = 0; k16 < 128; k16 += 16) {
        uint32_t bh[8][2];
#pragma unroll
        for (int ni = 0; ni < 8; ni++) {
            const __half* bp = Bs16 + (n0 + ni * 8 + gid) * LDA + k16 + tid4 * 2;
            bh[ni][0] = *reinterpret_cast<const uint32_t*>(bp);
            bh[ni][1] = *reinterpret_cast<const uint32_t*>(bp + 8);
        }
#pragma unroll
        for (int mi = 0; mi < 2; mi++) {
            const int r = m0 + mi * 16 + gid, c = k16 + tid4 * 2;
            uint32_t ah[4];
            ah[0] = *reinterpret_cast<const uint32_t*>(As16 + r * LDA + c);
            ah[1] = *reinterpret_cast<const uint32_t*>(As16 + (r + 8) * LDA + c);
            ah[2] = *reinterpret_cast<const uint32_t*>(As16 + r * LDA + c + 8);
            ah[3] = *reinterpret_cast<const uint32_t*>(As16 + (r + 8) * LDA + c + 8);
#pragma unroll
            for (int ni = 0; ni < 8; ni++) mma16816_f16(acc[mi][ni], ah, bh[ni]);
        }
    }
    __syncthreads();

#pragma unroll
    for (int mi = 0; mi < 2; mi++)
#pragma unroll
        for (int rr = 0; rr < 2; rr++) {
            int lr = m0 + mi * 16 + gid + rr * 8;
#pragma unroll
            for (int ni = 0; ni < 8; ni++) {
                int cn = n0 + ni * 8 + tid4 * 2;
                float2 bb = *reinterpret_cast<const float2*>(bm1 + cn);
                __half2 h = __floats2half2_rn(fmaxf(acc[mi][ni][rr * 2] + bb.x, 0.f),
                                              fmaxf(acc[mi][ni][rr * 2 + 1] + bb.y, 0.f));
                *reinterpret_cast<__half2*>(As16 + lr * LDA + cn) = h;
            }
        }
    __syncthreads();

    const int n02 = (wid & 1) * 32;
    float acc2[2][4][4];
#pragma unroll
    for (int mi = 0; mi < 2; mi++)
#pragma unroll
        for (int ni = 0; ni < 4; ni++)
#pragma unroll
            for (int j = 0; j < 4; j++) acc2[mi][ni][j] = 0.f;

    for (int kc = 0; kc < 128; kc += 64) {
        if (kc) __syncthreads();
#pragma unroll
        for (int it = 0; it < 4; it++) {
            int i = tid + it * 256;
            int n = i >> 4, q = (i & 15) * 4;
            *reinterpret_cast<uint2*>(B2 + n * LDB + q) =
                *reinterpret_cast<const uint2*>(w2f + n * 128 + kc + q);
        }
        __syncthreads();
#pragma unroll
        for (int k16 = 0; k16 < 64; k16 += 16) {
            uint32_t bh[4][2];
#pragma unroll
            for (int ni = 0; ni < 4; ni++) {
                const __half* bp = B2 + (n02 + ni * 8 + gid) * LDB + k16 + tid4 * 2;
                bh[ni][0] = *reinterpret_cast<const uint32_t*>(bp);
                bh[ni][1] = *reinterpret_cast<const uint32_t*>(bp + 8);
            }
#pragma unroll
            for (int mi = 0; mi < 2; mi++) {
                const int r = m0 + mi * 16 + gid, c = kc + k16 + tid4 * 2;
                uint32_t ah[4];
                ah[0] = *reinterpret_cast<const uint32_t*>(As16 + r * LDA + c);
                ah[1] = *reinterpret_cast<const uint32_t*>(As16 + (r + 8) * LDA + c);
                ah[2] = *reinterpret_cast<const uint32_t*>(As16 + r * LDA + c + 8);
                ah[3] = *reinterpret_cast<const uint32_t*>(As16 + (r + 8) * LDA + c + 8);
#pragma unroll
                for (int ni = 0; ni < 4; ni++) mma16816_f16(acc2[mi][ni], ah, bh[ni]);
            }
        }
    }

#pragma unroll
    for (int mi = 0; mi < 2; mi++)
#pragma unroll
        for (int rr = 0; rr < 2; rr++) {
            int r = row0 + m0 + mi * 16 + gid + rr * 8;
            if (r < N_NODES) {
#pragma unroll
                for (int ni = 0; ni < 4; ni++) {
                    int cn = n02 + ni * 8 + tid4 * 2;
                    float2 bb = *reinterpret_cast<const float2*>(bm2 + cn);
                    float2 o = make_float2(acc2[mi][ni][rr * 2] + bb.x,
                                           acc2[mi][ni][rr * 2 + 1] + bb.y);
                    *reinterpret_cast<float2*>(outext + (size_t)r * OUTD + cn) = o;
                }
            }
        }
}

// ---------------- launch ----------------
extern "C" void kernel_launch(void* const* d_in, const int* in_sizes, int n_in,
                              void* d_out, int out_size) {
    (void)in_sizes; (void)n_in; (void)out_size;
    const float* x   = (const float*)d_in[0];
    const int*   src = (const int*)d_in[1];
    const int*   dst = (const int*)d_in[2];
    const float* W0 = (const float*)d_in[3],  *b0 = (const float*)d_in[4];
    const float* g0 = (const float*)d_in[5],  *be0 = (const float*)d_in[6];
    const float* m0 = (const float*)d_in[7],  *v0 = (const float*)d_in[8];
    const float* W1 = (const float*)d_in[9],  *b1 = (const float*)d_in[10];
    const float* g1 = (const float*)d_in[11], *be1 = (const float*)d_in[12];
    const float* m1 = (const float*)d_in[13], *v1 = (const float*)d_in[14];
    const float* W2 = (const float*)d_in[15], *b2 = (const float*)d_in[16];
    const float* g2 = (const float*)d_in[17], *be2 = (const float*)d_in[18];
    const float* m2 = (const float*)d_in[19], *v2 = (const float*)d_in[20];
    const float* Wm1 = (const float*)d_in[21], *bm1 = (const float*)d_in[22];
    const float* Wm2 = (const float*)d_in[23], *bm2 = (const float*)d_in[24];
    float* out = (float*)d_out;

    const int NB_EDGE = (N_EDGES + 255) / 256;
    const int NB_GEMM = (N_NODES + 127) / 128;
    const int NB_AGG  = (N_NODES + 7) / 8;

    constexpr int SM_F = (128 * 72 + 128 * 72) * 2;     // 36864
    constexpr int SM_H = 69632 + 64 * 72 * 2;           // 78848

    cudaFuncSetAttribute(mma_gemm_f16_kernel<64, 0>,
                         cudaFuncAttributeMaxDynamicSharedMemorySize, SM_F);
    cudaFuncSetAttribute(mma_gemm_f16_kernel<128, 1>,
                         cudaFuncAttributeMaxDynamicSharedMemorySize, SM_F);
    cudaFuncSetAttribute(mlp_head_kernel,
                         cudaFuncAttributeMaxDynamicSharedMemorySize, SM_H);

    __half* wf_dev = nullptr;
    cudaGetSymbolAddress((void**)&wf_dev, g_wf16);

    // side stream for CSR build (g_cnt arrives pre-zeroed: BSS init on first call,
    // re-zeroed by fill_csr_kernel on every call)
    static cudaStream_t s2 = nullptr;
    static cudaEvent_t evFork = nullptr, evJoin = nullptr;
    if (s2 == nullptr) {
        cudaStreamCreateWithFlags(&s2, cudaStreamNonBlocking);
        cudaEventCreateWithFlags(&evFork, cudaEventDisableTiming);
        cudaEventCreateWithFlags(&evJoin, cudaEventDisableTiming);
    }

    cudaEventRecord(evFork, 0);
    cudaStreamWaitEvent(s2, evFork, 0);
    hist_kernel<<<NB_EDGE, 256, 0, s2>>>(dst);
    scan_dinv_kernel<<<1, 1024, 0, s2>>>();
    fill_csr_kernel<<<NB_EDGE, 256, 0, s2>>>(src, dst);
    cudaEventRecord(evJoin, s2);

    // main stream: weights + layer-0 GEMM (dinv-independent)
    prep_w_kernel<<<(5 * 16384 + 255) / 256, 256>>>(W0, W1, W2, Wm1, Wm2);
    mma_gemm_f16_kernel<64, 0><<<NB_GEMM, 256, SM_F>>>(x, wf_dev);

    cudaStreamWaitEvent(0, evJoin, 0);

    agg_bn_kernel<<<NB_AGG, 256>>>(b0, g0, be0, m0, v0);
    mma_gemm_f16_kernel<128, 1><<<NB_GEMM, 256, SM_F>>>(nullptr, wf_dev + 1 * 16384);
    agg_bn_kernel<<<NB_AGG, 256>>>(b1, g1, be1, m1, v1);
    mma_gemm_f16_kernel<128, 1><<<NB_GEMM, 256, SM_F>>>(nullptr, wf_dev + 2 * 16384);
    agg_bn_kernel<<<NB_AGG, 256>>>(b2, g2, be2, m2, v2);

    mlp_head_kernel<<<NB_GEMM, 256, SM_H>>>(bm1, bm2, wf_dev + 3 * 16384,
                                            wf_dev + 4 * 16384, out);
}